// round 16
// baseline (speedup 1.0000x reference)
#include <cuda_runtime.h>

#define NB   8
#define TENC 512
#define DIN  512
#define TDEC 150
#define OD   80
#define DR   1024
#define PREN 256
#define AT   128
#define LOCC 32
#define KF   31
#define GRID 148

// ---------------- device scratch (16B-aligned: float4 access) ----------------
__device__ __align__(16) float g_pm[NB*TENC*AT];       // proc_mem [b,t,a]
__device__ __align__(16) float g_G[AT*KF];             // fused loc filters
__device__ __align__(16) float g_prev[TDEC*NB*OD];     // teacher-forced prev outputs
__device__ __align__(16) float g_p1[TDEC*NB*PREN];
__device__ __align__(16) float g_p2[TDEC*NB*PREN];
__device__ __align__(16) float g_h0[2*NB*DR];          // ping-pong state
__device__ __align__(16) float g_c0[2*NB*DR];
__device__ __align__(16) float g_h1[2*NB*DR];
__device__ __align__(16) float g_c1[2*NB*DR];
__device__ __align__(16) float g_cum[NB*TENC];
__device__ __align__(16) float g_q[NB*AT];
__device__ __align__(16) float g_e[NB*TENC];
__device__ __align__(16) float g_attp[NB*8*DIN];       // attc partials [b][tc][d]
__device__ __align__(16) float g_attc[NB*DIN];         // reduced attc (for feat)
__device__ unsigned g_arr[GRID*32];                    // barrier arrival flags (128B apart)
__device__ unsigned g_rel;                             // barrier release token

__device__ __forceinline__ float sigf(float x){ return 1.f/(1.f + expf(-x)); }
__device__ __forceinline__ float wredsum(float v){
    v += __shfl_xor_sync(0xffffffffu, v, 16);
    v += __shfl_xor_sync(0xffffffffu, v, 8);
    v += __shfl_xor_sync(0xffffffffu, v, 4);
    v += __shfl_xor_sync(0xffffffffu, v, 2);
    v += __shfl_xor_sync(0xffffffffu, v, 1);
    return v;
}
__device__ __forceinline__ float dot4(float4 a, float4 b){
    return a.x*b.x + a.y*b.y + a.z*b.z + a.w*b.w;
}
// packed fp32x2 FMA (FFMA2): exact fp32 semantics, 2 MACs/instr
__device__ __forceinline__ void ffma2(unsigned long long &d, unsigned long long a, unsigned long long b){
    asm("fma.rn.f32x2 %0, %1, %2, %0;" : "+l"(d) : "l"(a), "l"(b));
}
__device__ __forceinline__ float pairsum(unsigned long long v){
    return __uint_as_float((unsigned)(v & 0xffffffffull)) + __uint_as_float((unsigned)(v >> 32));
}
struct U2 { unsigned long long a, b; };
__device__ __forceinline__ U2 ldu2(const float* p){
    union { float4 f; U2 u; } t;
    t.f = *(const float4*)p;
    return t.u;
}
__device__ __forceinline__ float tanha(float x){
    float y; asm("tanh.approx.f32 %0, %1;" : "=f"(y) : "f"(x)); return y;
}

// flag-based grid barrier: per-block arrival slot + block-0 release. No atomics.
__device__ __forceinline__ void gridbar(unsigned tok){
    __syncthreads();
    if (threadIdx.x < 32){
        if (threadIdx.x == 0){
            __threadfence();
            *(volatile unsigned*)&g_arr[blockIdx.x*32] = tok;
        }
        if (blockIdx.x == 0){
            for(;;){
                bool ok = true;
                for (int i = threadIdx.x; i < GRID; i += 32)
                    if (*(volatile unsigned*)&g_arr[i*32] < tok) ok = false;
                if (__all_sync(0xffffffffu, ok)) break;
            }
            if (threadIdx.x == 0){ __threadfence(); *(volatile unsigned*)&g_rel = tok; }
        } else if (threadIdx.x == 0){
            while (*(volatile unsigned*)&g_rel < tok) {}
            __threadfence();
        }
    }
    __syncthreads();
}

// ---------------- init (also resets barrier state for graph replays) ----------------
__global__ void k_init(const float* __restrict__ targets, const float* __restrict__ attn_b,
                       const float* __restrict__ W_loc, const float* __restrict__ filt){
    int i = blockIdx.x*blockDim.x + threadIdx.x;
    if (i == 0) g_rel = 0u;
    if (i < GRID*32) g_arr[i] = 0u;
    if (i < 2*NB*DR){ g_h0[i]=0.f; g_c0[i]=0.f; g_h1[i]=0.f; g_c1[i]=0.f; }
    if (i < NB*TENC) g_cum[i] = 0.f;
    if (i < NB*AT)   g_q[i]   = attn_b[i & (AT-1)];
    if (i < AT*KF){
        int a = i / KF, k = i - a*KF;
        float s = 0.f;
        #pragma unroll
        for (int c=0;c<LOCC;c++) s += W_loc[a*LOCC+c] * filt[c*KF+k];
        g_G[i] = s;
    }
    int tot = gridDim.x*blockDim.x;
    for (int p=i; p < TDEC*NB*OD; p += tot){
        int o = p % OD; int sb = p / OD; int b = sb % NB; int t = sb / NB;
        g_prev[p] = (t==0) ? 0.f : targets[(b*TDEC + (t-1))*OD + o];
    }
}

// ---------------- tiled GEMM: C[M,N] = A[M,K] * B[N,K]^T (+bias)(relu) ----------------
__global__ void __launch_bounds__(256) k_gemm(const float* __restrict__ A, int lda,
                const float* __restrict__ Bm, int ldb, float* __restrict__ C, int ldc,
                int M, int N, int K, const float* __restrict__ bias, int relu){
    __shared__ float As[64][17];
    __shared__ float Bs[64][17];
    int bm = blockIdx.x*64, bn = blockIdx.y*64;
    int tid = threadIdx.x;
    int tx = tid & 15, ty = tid >> 4;
    float acc[4][4];
    #pragma unroll
    for(int i=0;i<4;i++){ acc[i][0]=0.f; acc[i][1]=0.f; acc[i][2]=0.f; acc[i][3]=0.f; }
    for (int k0=0;k0<K;k0+=16){
        #pragma unroll
        for (int l=tid; l<1024; l+=256){
            int r = l >> 4, c = l & 15;
            int kk = k0 + c;
            int m = bm + r;
            As[r][c] = (m < M && kk < K) ? A[m*lda + kk] : 0.f;
            int n = bn + r;
            Bs[r][c] = (n < N && kk < K) ? Bm[n*ldb + kk] : 0.f;
        }
        __syncthreads();
        #pragma unroll
        for (int kk=0;kk<16;kk++){
            float a[4], bv[4];
            #pragma unroll
            for (int i=0;i<4;i++) a[i]  = As[ty*4+i][kk];
            #pragma unroll
            for (int j=0;j<4;j++) bv[j] = Bs[tx*4+j][kk];
            #pragma unroll
            for (int i=0;i<4;i++)
                #pragma unroll
                for (int j=0;j<4;j++) acc[i][j] += a[i]*bv[j];
        }
        __syncthreads();
    }
    #pragma unroll
    for (int i=0;i<4;i++){
        int m = bm + ty*4 + i;
        if (m >= M) continue;
        #pragma unroll
        for (int j=0;j<4;j++){
            int n = bn + tx*4 + j;
            if (n >= N) continue;
            float v = acc[i][j];
            if (bias) v += bias[n];
            if (relu) v = fmaxf(v, 0.f);
            C[m*ldc + n] = v;
        }
    }
}

// feat/stop projection tasks for step tstep (runs on blocks 128-147)
__device__ __forceinline__ void do_feat(int tstep, const float* h1base,
                const float* __restrict__ feat_W, const float* __restrict__ stop_W,
                const float* __restrict__ stop_b, float* __restrict__ out,
                int blk, int warp, int lane){
    int gw = (blk-128)*16 + warp;                     // 0..319
    for (int task = gw; task < 8*81; task += 320){
        int b = task / 81, r = task - b*81;
        const float* h1 = h1base + b*DR;
        const float* ac = g_attc + b*DIN;
        const float* wrow = (r < 80) ? (feat_W + r*(DR+DIN)) : stop_W;
        float s = 0.f;
        for (int k = lane*4; k < DR; k += 128)
            s += dot4(*(const float4*)(wrow + k), *(const float4*)(h1 + k));
        for (int k = lane*4; k < DIN; k += 128)
            s += dot4(*(const float4*)(wrow + DR + k), *(const float4*)(ac + k));
        s = wredsum(s);
        if (lane == 0){
            if (r < 80) out[(b*TDEC + tstep)*OD + r] = s;
            else        out[TDEC*NB*OD + b*TDEC + tstep] = s + stop_b[0];
        }
    }
}

// ---------------- persistent decoder: all 150 steps, 4 grid barriers/step ----------------
__global__ void __launch_bounds__(512, 1) k_decoder(
    const float* __restrict__ mem, const int* __restrict__ memlen,
    const float* __restrict__ attn_v,
    const float* __restrict__ Wi0, const float* __restrict__ Wh0, const float* __restrict__ bl0,
    const float* __restrict__ Wi1, const float* __restrict__ Wh1, const float* __restrict__ bl1,
    const float* __restrict__ feat_W, const float* __restrict__ stop_W, const float* __restrict__ stop_b,
    const float* __restrict__ W_q, const float* __restrict__ attn_b,
    float* __restrict__ out)
{
    // 16B alignment is REQUIRED: xs is read with ld.shared.v4 (misaligned-address
    // trap in R15 came from default 4B alignment + odd-sized neighbors).
    __shared__ __align__(16) float xs[NB*768];        // LSTM0 input vectors [b][768]
    __shared__ __align__(16) float G_s[AT*KF];
    __shared__ __align__(16) float v_s[AT];
    __shared__ __align__(16) float q_s[AT];
    __shared__ __align__(16) float cum_s[64];
    __shared__ __align__(16) float red[512];
    __shared__ __align__(16) float ws_s[64];
    __shared__ __align__(16) float sred[256];         // 16 warps x 16 reduced gate sums

    const int tid  = threadIdx.x;
    const int warp = tid >> 5, lane = tid & 31;
    const int blk  = blockIdx.x;
    unsigned tok = 0;

    for (int i = tid; i < AT*KF; i += 512) G_s[i] = g_G[i];
    if (tid < AT) v_s[tid] = attn_v[tid];
    __syncthreads();

    for (int t = 0; t < TDEC; t++){
        const int rb = t & 1, wb = rb ^ 1;

        // ---- P1: energies (blocks 0-127) || feat/stop for step t-1 (blocks 128-147) ----
        if (blk < 128){
            int b = blk >> 4, chunk = blk & 15, t0 = chunk*32;
            if (tid < 62){
                int tg = t0 - 15 + tid;
                cum_s[tid] = (tg >= 0 && tg < TENC) ? g_cum[b*TENC + tg] : 0.f;
            }
            if (tid < AT) q_s[tid] = g_q[b*AT + tid];
            __syncthreads();
            for (int tt = warp; tt < 32; tt += 16){
                int tg = t0 + tt;
                const float* pm = g_pm + (b*TENC + tg)*AT;
                float part = 0.f;
                #pragma unroll
                for (int i=0;i<4;i++){
                    int a = lane + 32*i;
                    float loc = 0.f;
                    #pragma unroll
                    for (int k=0;k<KF;k++) loc += cum_s[tt+k]*G_s[a*KF+k];
                    part += v_s[a]*tanha(pm[a] + q_s[a] + loc);
                }
                part = wredsum(part);
                if (lane == 0) g_e[b*TENC + tg] = part;
            }
        } else if (t > 0){
            // h1 of step t-1 lives in buffer (t-1 & 1)^1 == rb
            do_feat(t-1, g_h1 + rb*NB*DR, feat_W, stop_W, stop_b, out, blk, warp, lane);
        }
        gridbar(++tok);

        // ---- P2: softmax (redundant per chunk) + attc partials (blocks 0-63) ----
        if (blk < 64){
            int b = blk >> 3, tc = blk & 7;
            int i = tid;
            int len = memlen[b];
            float ev = (i < len) ? g_e[b*TENC + i] : -1e30f;
            red[i] = ev; __syncthreads();
            for (int s=256; s>0; s>>=1){ if (i < s) red[i] = fmaxf(red[i], red[i+s]); __syncthreads(); }
            float m = red[0]; __syncthreads();
            float ex = (i < len) ? expf(ev - m) : 0.f;
            red[i] = ex; __syncthreads();
            for (int s=256; s>0; s>>=1){ if (i < s) red[i] += red[i+s]; __syncthreads(); }
            float w = ex / red[0];
            if ((i >> 6) == tc) ws_s[i & 63] = w;    // this chunk's 64 weights
            if (tc == 0){
                g_cum[b*TENC + i] += w;
                out[TDEC*NB*OD + TDEC*NB + (b*TDEC + t)*TENC + i] = w;
            }
            __syncthreads();
            // partial attc over t-range [tc*64, tc*64+64)
            const float* mp = mem + (b*TENC + tc*64)*DIN + tid;
            float a0=0.f,a1=0.f,a2=0.f,a3=0.f,a4=0.f,a5=0.f,a6=0.f,a7=0.f;
            #pragma unroll
            for (int u=0;u<64;u+=8){
                a0 += ws_s[u+0]*mp[(u+0)*DIN];
                a1 += ws_s[u+1]*mp[(u+1)*DIN];
                a2 += ws_s[u+2]*mp[(u+2)*DIN];
                a3 += ws_s[u+3]*mp[(u+3)*DIN];
                a4 += ws_s[u+4]*mp[(u+4)*DIN];
                a5 += ws_s[u+5]*mp[(u+5)*DIN];
                a6 += ws_s[u+6]*mp[(u+6)*DIN];
                a7 += ws_s[u+7]*mp[(u+7)*DIN];
            }
            g_attp[(b*8 + tc)*DIN + tid] = ((a0+a1)+(a2+a3)) + ((a4+a5)+(a6+a7));
        }
        gridbar(++tok);

        // ---- P3: LSTM0 (blocks 0-127) || attc reduce for feat (blocks 128-135) ----
        if (blk < 128){
            // stage x = [sum(attc partials)(512) | p2(256)] into smem
            for (int idx = tid; idx < NB*768; idx += 512){
                int b = idx / 768, d = idx - b*768;
                float v;
                if (d < 512){
                    v = 0.f;
                    #pragma unroll
                    for (int tc=0; tc<8; tc++) v += g_attp[(b*8+tc)*DIN + d];
                } else {
                    v = g_p2[(t*NB + b)*PREN + (d - 512)];
                }
                xs[idx] = v;
            }
            __syncthreads();
            int j  = blk*8 + (warp >> 1);
            int g2 = warp & 1;                       // gates {2*g2, 2*g2+1}
            const float* h0r = g_h0 + rb*NB*DR;
            unsigned long long acc[2][8];
            #pragma unroll
            for (int g=0;g<2;g++)
                #pragma unroll
                for (int b=0;b<8;b++) acc[g][b] = 0ull;
            const float* W0 = Wi0 + (unsigned)(j + (2*g2  )*1024)*768;
            const float* W1 = Wi0 + (unsigned)(j + (2*g2+1)*1024)*768;
            #pragma unroll
            for (int c=0;c<6;c++){
                int k = c*128 + lane*4;
                U2 w0 = ldu2(W0 + k), w1 = ldu2(W1 + k);
                #pragma unroll
                for (int b=0;b<8;b++){
                    U2 x = ldu2(xs + b*768 + k);
                    ffma2(acc[0][b], w0.a, x.a); ffma2(acc[0][b], w0.b, x.b);
                    ffma2(acc[1][b], w1.a, x.a); ffma2(acc[1][b], w1.b, x.b);
                }
            }
            const float* H0 = Wh0 + (unsigned)(j + (2*g2  )*1024)*1024;
            const float* H1 = Wh0 + (unsigned)(j + (2*g2+1)*1024)*1024;
            #pragma unroll
            for (int c=0;c<8;c++){
                int k = c*128 + lane*4;
                U2 w0 = ldu2(H0 + k), w1 = ldu2(H1 + k);
                #pragma unroll
                for (int b=0;b<8;b++){
                    U2 x = ldu2(h0r + b*DR + k);
                    ffma2(acc[0][b], w0.a, x.a); ffma2(acc[0][b], w0.b, x.b);
                    ffma2(acc[1][b], w1.a, x.a); ffma2(acc[1][b], w1.b, x.b);
                }
            }
            float red16 = 0.f;
            #pragma unroll
            for (int g=0;g<2;g++)
                #pragma unroll
                for (int b=0;b<8;b++){
                    float v = wredsum(pairsum(acc[g][b]));
                    if (lane == g*8 + b) red16 = v;
                }
            if (lane < 16) sred[warp*16 + lane] = red16;
            __syncthreads();
            if (warp < 8){
                int jj = blk*8 + warp;
                int gate = lane >> 3, b = lane & 7;
                float myg = sred[(warp*2 + (gate>>1))*16 + (gate&1)*8 + b] + bl0[gate*1024 + jj];
                float fv = __shfl_sync(0xffffffffu, myg, lane+8);
                float gv = __shfl_sync(0xffffffffu, myg, lane+16);
                float ov = __shfl_sync(0xffffffffu, myg, lane+24);
                if (lane < 8){
                    float hold = h0r[b*DR + jj];
                    float cold = g_c0[rb*NB*DR + b*DR + jj];
                    float cn = sigf(fv)*cold + sigf(myg)*tanhf(gv);
                    float hn = sigf(ov)*tanhf(cn);
                    g_h0[wb*NB*DR + b*DR + jj] = 0.9f*hn + 0.1f*hold;
                    g_c0[wb*NB*DR + b*DR + jj] = 0.9f*cn + 0.1f*cold;
                }
            }
        } else if (blk < 136){
            int b = blk - 128;
            float v = 0.f;
            #pragma unroll
            for (int tc=0; tc<8; tc++) v += g_attp[(b*8+tc)*DIN + tid];
            g_attc[b*DIN + tid] = v;
        }
        gridbar(++tok);

        // ---- P4: LSTM1 (blocks 0-127) || q projection for next step (blocks 128-147) ----
        if (blk < 128){
            int j  = blk*8 + (warp >> 1);
            int g2 = warp & 1;
            const float* h0n = g_h0 + wb*NB*DR;
            const float* h1r = g_h1 + rb*NB*DR;
            unsigned long long acc[2][8];
            #pragma unroll
            for (int g=0;g<2;g++)
                #pragma unroll
                for (int b=0;b<8;b++) acc[g][b] = 0ull;
            const float* W0 = Wi1 + (unsigned)(j + (2*g2  )*1024)*1024;
            const float* W1 = Wi1 + (unsigned)(j + (2*g2+1)*1024)*1024;
            #pragma unroll
            for (int c=0;c<8;c++){
                int k = c*128 + lane*4;
                U2 w0 = ldu2(W0 + k), w1 = ldu2(W1 + k);
                #pragma unroll
                for (int b=0;b<8;b++){
                    U2 x = ldu2(h0n + b*DR + k);
                    ffma2(acc[0][b], w0.a, x.a); ffma2(acc[0][b], w0.b, x.b);
                    ffma2(acc[1][b], w1.a, x.a); ffma2(acc[1][b], w1.b, x.b);
                }
            }
            const float* H0 = Wh1 + (unsigned)(j + (2*g2  )*1024)*1024;
            const float* H1 = Wh1 + (unsigned)(j + (2*g2+1)*1024)*1024;
            #pragma unroll
            for (int c=0;c<8;c++){
                int k = c*128 + lane*4;
                U2 w0 = ldu2(H0 + k), w1 = ldu2(H1 + k);
                #pragma unroll
                for (int b=0;b<8;b++){
                    U2 x = ldu2(h1r + b*DR + k);
                    ffma2(acc[0][b], w0.a, x.a); ffma2(acc[0][b], w0.b, x.b);
                    ffma2(acc[1][b], w1.a, x.a); ffma2(acc[1][b], w1.b, x.b);
                }
            }
            float red16 = 0.f;
            #pragma unroll
            for (int g=0;g<2;g++)
                #pragma unroll
                for (int b=0;b<8;b++){
                    float v = wredsum(pairsum(acc[g][b]));
                    if (lane == g*8 + b) red16 = v;
                }
            if (lane < 16) sred[warp*16 + lane] = red16;
            __syncthreads();
            if (warp < 8){
                int jj = blk*8 + warp;
                int gate = lane >> 3, b = lane & 7;
                float myg = sred[(warp*2 + (gate>>1))*16 + (gate&1)*8 + b] + bl1[gate*1024 + jj];
                float fv = __shfl_sync(0xffffffffu, myg, lane+8);
                float gv = __shfl_sync(0xffffffffu, myg, lane+16);
                float ov = __shfl_sync(0xffffffffu, myg, lane+24);
                if (lane < 8){
                    float hold = h1r[b*DR + jj];
                    float cold = g_c1[rb*NB*DR + b*DR + jj];
                    float cn = sigf(fv)*cold + sigf(myg)*tanhf(gv);
                    float hn = sigf(ov)*tanhf(cn);
                    g_h1[wb*NB*DR + b*DR + jj] = 0.9f*hn + 0.1f*hold;
                    g_c1[wb*NB*DR + b*DR + jj] = 0.9f*cn + 0.1f*cold;
                }
            }
        } else {
            // q[b,a] = W_q[a] . h0_new[b] + attn_b[a]   (1024 warp tasks)
            const float* h0n = g_h0 + wb*NB*DR;
            int gw = (blk-128)*16 + warp;
            for (int task = gw; task < NB*AT; task += 320){
                int b = task >> 7, a = task & (AT-1);
                const float* wrow = W_q + a*DR;
                const float* hv = h0n + b*DR;
                float s = 0.f;
                for (int k = lane*4; k < DR; k += 128)
                    s += dot4(*(const float4*)(wrow + k), *(const float4*)(hv + k));
                s = wredsum(s);
                if (lane == 0) g_q[b*AT + a] = s + attn_b[a];
            }
        }
        gridbar(++tok);
    }

    // tail: feat/stop for the last step (h1 buffer = (149&1)^1 = 0)
    if (blk >= 128)
        do_feat(TDEC-1, g_h1 + 0, feat_W, stop_W, stop_b, out, blk, warp, lane);
}

// ---------------- host launch ----------------
extern "C" void kernel_launch(void* const* d_in, const int* in_sizes, int n_in,
                              void* d_out, int out_size) {
    const float* memory  = (const float*)d_in[0];
    const int*   memlen  = (const int*)  d_in[1];
    const float* targets = (const float*)d_in[2];
    const float* W_mem   = (const float*)d_in[3];
    const float* W_q     = (const float*)d_in[4];
    const float* W_loc   = (const float*)d_in[5];
    const float* filt    = (const float*)d_in[6];
    const float* attn_v  = (const float*)d_in[7];
    const float* attn_b  = (const float*)d_in[8];
    const float* pre_W1  = (const float*)d_in[9];
    const float* pre_b1  = (const float*)d_in[10];
    const float* pre_W2  = (const float*)d_in[11];
    const float* pre_b2  = (const float*)d_in[12];
    const float* Wi0     = (const float*)d_in[13];
    const float* Wh0     = (const float*)d_in[14];
    const float* bl0     = (const float*)d_in[15];
    const float* Wi1     = (const float*)d_in[16];
    const float* Wh1     = (const float*)d_in[17];
    const float* bl1     = (const float*)d_in[18];
    const float* feat_W  = (const float*)d_in[19];
    const float* stop_W  = (const float*)d_in[20];
    const float* stop_b  = (const float*)d_in[21];
    float* out = (float*)d_out;

    // GB300/ATS: host-side &symbol is the host shadow; resolve device addresses.
    float *pm_d = nullptr, *prev_d = nullptr, *p1_d = nullptr, *p2_d = nullptr;
    cudaGetSymbolAddress((void**)&pm_d,   g_pm);
    cudaGetSymbolAddress((void**)&prev_d, g_prev);
    cudaGetSymbolAddress((void**)&p1_d,   g_p1);
    cudaGetSymbolAddress((void**)&p2_d,   g_p2);

    k_init<<<64, 256>>>(targets, attn_b, W_loc, filt);
    k_gemm<<<dim3(64,2), 256>>>(memory, DIN, W_mem, DIN, pm_d, AT, NB*TENC, AT, DIN, nullptr, 0);
    k_gemm<<<dim3(19,4), 256>>>(prev_d, OD,   pre_W1, OD,   p1_d, PREN, TDEC*NB, PREN, OD,   pre_b1, 1);
    k_gemm<<<dim3(19,4), 256>>>(p1_d,   PREN, pre_W2, PREN, p2_d, PREN, TDEC*NB, PREN, PREN, pre_b2, 1);

    k_decoder<<<GRID, 512>>>(memory, memlen, attn_v,
                             Wi0, Wh0, bl0, Wi1, Wh1, bl1,
                             feat_W, stop_W, stop_b, W_q, attn_b, out);
}

// round 17
// speedup vs baseline: 1.0593x; 1.0593x over previous
#include <cuda_runtime.h>

#define NB   8
#define TENC 512
#define DIN  512
#define TDEC 150
#define OD   80
#define DR   1024
#define PREN 256
#define AT   128
#define LOCC 32
#define KF   31
#define GRID 148

// ---------------- device scratch (16B-aligned: float4 access) ----------------
__device__ __align__(16) float g_pm[NB*TENC*AT];       // proc_mem [b,t,a]
__device__ __align__(16) float g_G[AT*KF];             // fused loc filters
__device__ __align__(16) float g_prev[TDEC*NB*OD];     // teacher-forced prev outputs
__device__ __align__(16) float g_p1[TDEC*NB*PREN];
__device__ __align__(16) float g_p2[TDEC*NB*PREN];
__device__ __align__(16) float g_h0[2*NB*DR];          // ping-pong state
__device__ __align__(16) float g_c0[2*NB*DR];
__device__ __align__(16) float g_h1[2*NB*DR];
__device__ __align__(16) float g_c1[2*NB*DR];
__device__ __align__(16) float g_cum[NB*TENC];
__device__ __align__(16) float g_q[NB*AT];
__device__ __align__(16) float g_e[NB*TENC];
__device__ __align__(16) float g_attc2[2*NB*DIN];      // att_c, parity ping-pong
__device__ unsigned g_arr[GRID*32];                    // barrier arrival flags (128B apart)
__device__ unsigned g_rel;                             // barrier release token

__device__ __forceinline__ float sigf(float x){ return 1.f/(1.f + expf(-x)); }
__device__ __forceinline__ float wredsum(float v){
    v += __shfl_xor_sync(0xffffffffu, v, 16);
    v += __shfl_xor_sync(0xffffffffu, v, 8);
    v += __shfl_xor_sync(0xffffffffu, v, 4);
    v += __shfl_xor_sync(0xffffffffu, v, 2);
    v += __shfl_xor_sync(0xffffffffu, v, 1);
    return v;
}
__device__ __forceinline__ float dot4(float4 a, float4 b){
    return a.x*b.x + a.y*b.y + a.z*b.z + a.w*b.w;
}
// packed fp32x2 FMA (FFMA2): exact fp32 semantics, 2 MACs/instr
__device__ __forceinline__ void ffma2(unsigned long long &d, unsigned long long a, unsigned long long b){
    asm("fma.rn.f32x2 %0, %1, %2, %0;" : "+l"(d) : "l"(a), "l"(b));
}
__device__ __forceinline__ float pairsum(unsigned long long v){
    return __uint_as_float((unsigned)(v & 0xffffffffull)) + __uint_as_float((unsigned)(v >> 32));
}
struct U2 { unsigned long long a, b; };
__device__ __forceinline__ U2 ldu2(const float* p){
    union { float4 f; U2 u; } t;
    t.f = *(const float4*)p;
    return t.u;
}
__device__ __forceinline__ float tanha(float x){
    float y; asm("tanh.approx.f32 %0, %1;" : "=f"(y) : "f"(x)); return y;
}

// flag-based grid barrier: per-block arrival slot + block-0 release. No atomics.
__device__ __forceinline__ void gridbar(unsigned tok){
    __syncthreads();
    if (threadIdx.x < 32){
        if (threadIdx.x == 0){
            __threadfence();
            *(volatile unsigned*)&g_arr[blockIdx.x*32] = tok;
        }
        if (blockIdx.x == 0){
            for(;;){
                bool ok = true;
                for (int i = threadIdx.x; i < GRID; i += 32)
                    if (*(volatile unsigned*)&g_arr[i*32] < tok) ok = false;
                if (__all_sync(0xffffffffu, ok)) break;
            }
            if (threadIdx.x == 0){ __threadfence(); *(volatile unsigned*)&g_rel = tok; }
        } else if (threadIdx.x == 0){
            while (*(volatile unsigned*)&g_rel < tok) {}
            __threadfence();
        }
    }
    __syncthreads();
}

// ---------------- init (also resets barrier state for graph replays) ----------------
__global__ void k_init(const float* __restrict__ targets, const float* __restrict__ attn_b,
                       const float* __restrict__ W_loc, const float* __restrict__ filt){
    int i = blockIdx.x*blockDim.x + threadIdx.x;
    if (i == 0) g_rel = 0u;
    if (i < GRID*32) g_arr[i] = 0u;
    if (i < 2*NB*DR){ g_h0[i]=0.f; g_c0[i]=0.f; g_h1[i]=0.f; g_c1[i]=0.f; }
    if (i < NB*TENC) g_cum[i] = 0.f;
    if (i < NB*AT)   g_q[i]   = attn_b[i & (AT-1)];
    if (i < AT*KF){
        int a = i / KF, k = i - a*KF;
        float s = 0.f;
        #pragma unroll
        for (int c=0;c<LOCC;c++) s += W_loc[a*LOCC+c] * filt[c*KF+k];
        g_G[i] = s;
    }
    int tot = gridDim.x*blockDim.x;
    for (int p=i; p < TDEC*NB*OD; p += tot){
        int o = p % OD; int sb = p / OD; int b = sb % NB; int t = sb / NB;
        g_prev[p] = (t==0) ? 0.f : targets[(b*TDEC + (t-1))*OD + o];
    }
}

// ---------------- tiled GEMM: C[M,N] = A[M,K] * B[N,K]^T (+bias)(relu) ----------------
__global__ void __launch_bounds__(256) k_gemm(const float* __restrict__ A, int lda,
                const float* __restrict__ Bm, int ldb, float* __restrict__ C, int ldc,
                int M, int N, int K, const float* __restrict__ bias, int relu){
    __shared__ float As[64][17];
    __shared__ float Bs[64][17];
    int bm = blockIdx.x*64, bn = blockIdx.y*64;
    int tid = threadIdx.x;
    int tx = tid & 15, ty = tid >> 4;
    float acc[4][4];
    #pragma unroll
    for(int i=0;i<4;i++){ acc[i][0]=0.f; acc[i][1]=0.f; acc[i][2]=0.f; acc[i][3]=0.f; }
    for (int k0=0;k0<K;k0+=16){
        #pragma unroll
        for (int l=tid; l<1024; l+=256){
            int r = l >> 4, c = l & 15;
            int kk = k0 + c;
            int m = bm + r;
            As[r][c] = (m < M && kk < K) ? A[m*lda + kk] : 0.f;
            int n = bn + r;
            Bs[r][c] = (n < N && kk < K) ? Bm[n*ldb + kk] : 0.f;
        }
        __syncthreads();
        #pragma unroll
        for (int kk=0;kk<16;kk++){
            float a[4], bv[4];
            #pragma unroll
            for (int i=0;i<4;i++) a[i]  = As[ty*4+i][kk];
            #pragma unroll
            for (int j=0;j<4;j++) bv[j] = Bs[tx*4+j][kk];
            #pragma unroll
            for (int i=0;i<4;i++)
                #pragma unroll
                for (int j=0;j<4;j++) acc[i][j] += a[i]*bv[j];
        }
        __syncthreads();
    }
    #pragma unroll
    for (int i=0;i<4;i++){
        int m = bm + ty*4 + i;
        if (m >= M) continue;
        #pragma unroll
        for (int j=0;j<4;j++){
            int n = bn + tx*4 + j;
            if (n >= N) continue;
            float v = acc[i][j];
            if (bias) v += bias[n];
            if (relu) v = fmaxf(v, 0.f);
            C[m*ldc + n] = v;
        }
    }
}

// feat/stop projection tasks for step tstep (runs on blocks 128-147)
__device__ __forceinline__ void do_feat(int tstep, const float* h1base, const float* acbase,
                const float* __restrict__ feat_W, const float* __restrict__ stop_W,
                const float* __restrict__ stop_b, float* __restrict__ out,
                int blk, int warp, int lane){
    int gw = (blk-128)*16 + warp;                     // 0..319
    for (int task = gw; task < 8*81; task += 320){
        int b = task / 81, r = task - b*81;
        const float* h1 = h1base + b*DR;
        const float* ac = acbase + b*DIN;
        const float* wrow = (r < 80) ? (feat_W + r*(DR+DIN)) : stop_W;
        float s = 0.f;
        for (int k = lane*4; k < DR; k += 128)
            s += dot4(*(const float4*)(wrow + k), *(const float4*)(h1 + k));
        for (int k = lane*4; k < DIN; k += 128)
            s += dot4(*(const float4*)(wrow + DR + k), *(const float4*)(ac + k));
        s = wredsum(s);
        if (lane == 0){
            if (r < 80) out[(b*TDEC + tstep)*OD + r] = s;
            else        out[TDEC*NB*OD + b*TDEC + tstep] = s + stop_b[0];
        }
    }
}

// ---------------- persistent decoder: all 150 steps, 4 grid barriers/step ----------------
__global__ void __launch_bounds__(512, 1) k_decoder(
    const float* __restrict__ mem, const int* __restrict__ memlen,
    const float* __restrict__ attn_v,
    const float* __restrict__ Wi0, const float* __restrict__ Wh0, const float* __restrict__ bl0,
    const float* __restrict__ Wi1, const float* __restrict__ Wh1, const float* __restrict__ bl1,
    const float* __restrict__ feat_W, const float* __restrict__ stop_W, const float* __restrict__ stop_b,
    const float* __restrict__ W_q, const float* __restrict__ attn_b,
    float* __restrict__ out)
{
    __shared__ __align__(16) float G_s[AT*KF];
    __shared__ __align__(16) float v_s[AT];
    __shared__ __align__(16) float q_s[AT];
    __shared__ __align__(16) float cum_s[64];
    __shared__ __align__(16) float red[512];
    __shared__ __align__(16) float ws_s[64];
    __shared__ __align__(16) float sred[512];         // 16 warps x 32 reduced gate sums

    const int tid  = threadIdx.x;
    const int warp = tid >> 5, lane = tid & 31;
    const int blk  = blockIdx.x;
    unsigned tok = 0;

    for (int i = tid; i < AT*KF; i += 512) G_s[i] = g_G[i];
    if (tid < AT) v_s[tid] = attn_v[tid];
    __syncthreads();

    for (int t = 0; t < TDEC; t++){
        const int rb = t & 1, wb = rb ^ 1;

        // ---- P1: energies + zero attc buf[rb] (blocks 0-127) || feat/stop t-1 (128-147) ----
        if (blk < 128){
            if (tid < 32) g_attc2[rb*NB*DIN + blk*32 + tid] = 0.f;   // attc(t) accumulator
            int b = blk >> 4, chunk = blk & 15, t0 = chunk*32;
            if (tid < 62){
                int tg = t0 - 15 + tid;
                cum_s[tid] = (tg >= 0 && tg < TENC) ? g_cum[b*TENC + tg] : 0.f;
            }
            if (tid < AT) q_s[tid] = g_q[b*AT + tid];
            __syncthreads();
            for (int tt = warp; tt < 32; tt += 16){
                int tg = t0 + tt;
                const float* pm = g_pm + (b*TENC + tg)*AT;
                float part = 0.f;
                #pragma unroll
                for (int i=0;i<4;i++){
                    int a = lane + 32*i;
                    float loc = 0.f;
                    #pragma unroll
                    for (int k=0;k<KF;k++) loc += cum_s[tt+k]*G_s[a*KF+k];
                    part += v_s[a]*tanha(pm[a] + q_s[a] + loc);
                }
                part = wredsum(part);
                if (lane == 0) g_e[b*TENC + tg] = part;
            }
        } else if (t > 0){
            // h1(t-1) in buffer rb; attc(t-1) in buffer wb
            do_feat(t-1, g_h1 + rb*NB*DR, g_attc2 + wb*NB*DIN,
                    feat_W, stop_W, stop_b, out, blk, warp, lane);
        }
        gridbar(++tok);

        // ---- P2: softmax (redundant per chunk) + attc via REDG atomics (blocks 0-63) ----
        if (blk < 64){
            int b = blk >> 3, tc = blk & 7;
            int i = tid;
            int len = memlen[b];
            float ev = (i < len) ? g_e[b*TENC + i] : -1e30f;
            red[i] = ev; __syncthreads();
            for (int s=256; s>0; s>>=1){ if (i < s) red[i] = fmaxf(red[i], red[i+s]); __syncthreads(); }
            float m = red[0]; __syncthreads();
            float ex = (i < len) ? expf(ev - m) : 0.f;
            red[i] = ex; __syncthreads();
            for (int s=256; s>0; s>>=1){ if (i < s) red[i] += red[i+s]; __syncthreads(); }
            float w = ex / red[0];
            if ((i >> 6) == tc) ws_s[i & 63] = w;    // this chunk's 64 weights
            if (tc == 0){
                g_cum[b*TENC + i] += w;
                out[TDEC*NB*OD + TDEC*NB + (b*TDEC + t)*TENC + i] = w;
            }
            __syncthreads();
            // partial attc over t-range [tc*64, tc*64+64)
            const float* mp = mem + (b*TENC + tc*64)*DIN + tid;
            float a0=0.f,a1=0.f,a2=0.f,a3=0.f,a4=0.f,a5=0.f,a6=0.f,a7=0.f;
            #pragma unroll
            for (int u=0;u<64;u+=8){
                a0 += ws_s[u+0]*mp[(u+0)*DIN];
                a1 += ws_s[u+1]*mp[(u+1)*DIN];
                a2 += ws_s[u+2]*mp[(u+2)*DIN];
                a3 += ws_s[u+3]*mp[(u+3)*DIN];
                a4 += ws_s[u+4]*mp[(u+4)*DIN];
                a5 += ws_s[u+5]*mp[(u+5)*DIN];
                a6 += ws_s[u+6]*mp[(u+6)*DIN];
                a7 += ws_s[u+7]*mp[(u+7)*DIN];
            }
            atomicAdd(&g_attc2[rb*NB*DIN + b*DIN + tid],
                      ((a0+a1)+(a2+a3)) + ((a4+a5)+(a6+a7)));
        }
        gridbar(++tok);

        // ---- P3: LSTM0 (blocks 0-127; 2-warp k-split per j; acc[4][8] f32x2) ----
        if (blk < 128){
            int j    = blk*8 + (warp >> 1);
            int half = warp & 1;
            const float* h0r = g_h0 + rb*NB*DR;
            const float* A   = g_attc2 + rb*NB*DIN;
            const float* P   = g_p2 + t*NB*PREN;
            unsigned long long acc[4][8];
            #pragma unroll
            for (int g=0;g<4;g++)
                #pragma unroll
                for (int b=0;b<8;b++) acc[g][b] = 0ull;
            const float* W0 = Wi0 + (unsigned)(j         )*768;
            const float* W1 = Wi0 + (unsigned)(j + 1024  )*768;
            const float* W2 = Wi0 + (unsigned)(j + 2048  )*768;
            const float* W3 = Wi0 + (unsigned)(j + 3072  )*768;
            #pragma unroll
            for (int c=0;c<3;c++){                      // input x = [attc|p2], k-half of 768
                int k = half*384 + c*128 + lane*4;
                U2 w0=ldu2(W0+k), w1=ldu2(W1+k), w2=ldu2(W2+k), w3=ldu2(W3+k);
                #pragma unroll
                for (int b=0;b<8;b++){
                    U2 x = (k < 512) ? ldu2(A + b*DIN + k) : ldu2(P + b*PREN + (k-512));
                    ffma2(acc[0][b], w0.a, x.a); ffma2(acc[0][b], w0.b, x.b);
                    ffma2(acc[1][b], w1.a, x.a); ffma2(acc[1][b], w1.b, x.b);
                    ffma2(acc[2][b], w2.a, x.a); ffma2(acc[2][b], w2.b, x.b);
                    ffma2(acc[3][b], w3.a, x.a); ffma2(acc[3][b], w3.b, x.b);
                }
            }
            const float* H0 = Wh0 + (unsigned)(j         )*1024;
            const float* H1 = Wh0 + (unsigned)(j + 1024  )*1024;
            const float* H2 = Wh0 + (unsigned)(j + 2048  )*1024;
            const float* H3 = Wh0 + (unsigned)(j + 3072  )*1024;
            #pragma unroll
            for (int c=0;c<4;c++){                      // hidden, k-half of 1024
                int k = half*512 + c*128 + lane*4;
                U2 w0=ldu2(H0+k), w1=ldu2(H1+k), w2=ldu2(H2+k), w3=ldu2(H3+k);
                #pragma unroll
                for (int b=0;b<8;b++){
                    U2 x = ldu2(h0r + b*DR + k);
                    ffma2(acc[0][b], w0.a, x.a); ffma2(acc[0][b], w0.b, x.b);
                    ffma2(acc[1][b], w1.a, x.a); ffma2(acc[1][b], w1.b, x.b);
                    ffma2(acc[2][b], w2.a, x.a); ffma2(acc[2][b], w2.b, x.b);
                    ffma2(acc[3][b], w3.a, x.a); ffma2(acc[3][b], w3.b, x.b);
                }
            }
            float myg = 0.f;
            #pragma unroll
            for (int g=0;g<4;g++)
                #pragma unroll
                for (int b=0;b<8;b++){
                    float v = wredsum(pairsum(acc[g][b]));
                    if (lane == g*8 + b) myg = v;
                }
            sred[warp*32 + lane] = myg;
            __syncthreads();
            if (half == 0){
                myg += sred[(warp+1)*32 + lane];
                myg += bl0[(lane>>3)*1024 + j];
                float fv = __shfl_sync(0xffffffffu, myg, lane+8);
                float gv = __shfl_sync(0xffffffffu, myg, lane+16);
                float ov = __shfl_sync(0xffffffffu, myg, lane+24);
                if (lane < 8){
                    int b = lane;
                    float hold = h0r[b*DR + j];
                    float cold = g_c0[rb*NB*DR + b*DR + j];
                    float cn = sigf(fv)*cold + sigf(myg)*tanhf(gv);
                    float hn = sigf(ov)*tanhf(cn);
                    g_h0[wb*NB*DR + b*DR + j] = 0.9f*hn + 0.1f*hold;
                    g_c0[wb*NB*DR + b*DR + j] = 0.9f*cn + 0.1f*cold;
                }
            }
        }
        gridbar(++tok);

        // ---- P4: LSTM1 (blocks 0-127) || q projection for next step (blocks 128-147) ----
        if (blk < 128){
            int j    = blk*8 + (warp >> 1);
            int half = warp & 1;
            const float* h0n = g_h0 + wb*NB*DR;
            const float* h1r = g_h1 + rb*NB*DR;
            unsigned long long acc[4][8];
            #pragma unroll
            for (int g=0;g<4;g++)
                #pragma unroll
                for (int b=0;b<8;b++) acc[g][b] = 0ull;
            {
                const float* W0 = Wi1 + (unsigned)(j         )*1024;
                const float* W1 = Wi1 + (unsigned)(j + 1024  )*1024;
                const float* W2 = Wi1 + (unsigned)(j + 2048  )*1024;
                const float* W3 = Wi1 + (unsigned)(j + 3072  )*1024;
                #pragma unroll
                for (int c=0;c<4;c++){
                    int k = half*512 + c*128 + lane*4;
                    U2 w0=ldu2(W0+k), w1=ldu2(W1+k), w2=ldu2(W2+k), w3=ldu2(W3+k);
                    #pragma unroll
                    for (int b=0;b<8;b++){
                        U2 x = ldu2(h0n + b*DR + k);
                        ffma2(acc[0][b], w0.a, x.a); ffma2(acc[0][b], w0.b, x.b);
                        ffma2(acc[1][b], w1.a, x.a); ffma2(acc[1][b], w1.b, x.b);
                        ffma2(acc[2][b], w2.a, x.a); ffma2(acc[2][b], w2.b, x.b);
                        ffma2(acc[3][b], w3.a, x.a); ffma2(acc[3][b], w3.b, x.b);
                    }
                }
            }
            {
                const float* H0 = Wh1 + (unsigned)(j         )*1024;
                const float* H1 = Wh1 + (unsigned)(j + 1024  )*1024;
                const float* H2 = Wh1 + (unsigned)(j + 2048  )*1024;
                const float* H3 = Wh1 + (unsigned)(j + 3072  )*1024;
                #pragma unroll
                for (int c=0;c<4;c++){
                    int k = half*512 + c*128 + lane*4;
                    U2 w0=ldu2(H0+k), w1=ldu2(H1+k), w2=ldu2(H2+k), w3=ldu2(H3+k);
                    #pragma unroll
                    for (int b=0;b<8;b++){
                        U2 x = ldu2(h1r + b*DR + k);
                        ffma2(acc[0][b], w0.a, x.a); ffma2(acc[0][b], w0.b, x.b);
                        ffma2(acc[1][b], w1.a, x.a); ffma2(acc[1][b], w1.b, x.b);
                        ffma2(acc[2][b], w2.a, x.a); ffma2(acc[2][b], w2.b, x.b);
                        ffma2(acc[3][b], w3.a, x.a); ffma2(acc[3][b], w3.b, x.b);
                    }
                }
            }
            float myg = 0.f;
            #pragma unroll
            for (int g=0;g<4;g++)
                #pragma unroll
                for (int b=0;b<8;b++){
                    float v = wredsum(pairsum(acc[g][b]));
                    if (lane == g*8 + b) myg = v;
                }
            sred[warp*32 + lane] = myg;
            __syncthreads();
            if (half == 0){
                myg += sred[(warp+1)*32 + lane];
                myg += bl1[(lane>>3)*1024 + j];
                float fv = __shfl_sync(0xffffffffu, myg, lane+8);
                float gv = __shfl_sync(0xffffffffu, myg, lane+16);
                float ov = __shfl_sync(0xffffffffu, myg, lane+24);
                if (lane < 8){
                    int b = lane;
                    float hold = h1r[b*DR + j];
                    float cold = g_c1[rb*NB*DR + b*DR + j];
                    float cn = sigf(fv)*cold + sigf(myg)*tanhf(gv);
                    float hn = sigf(ov)*tanhf(cn);
                    g_h1[wb*NB*DR + b*DR + j] = 0.9f*hn + 0.1f*hold;
                    g_c1[wb*NB*DR + b*DR + j] = 0.9f*cn + 0.1f*cold;
                }
            }
        } else {
            // q[b,a] = W_q[a] . h0_new[b] + attn_b[a]   (1024 warp tasks on 320 warps)
            const float* h0n = g_h0 + wb*NB*DR;
            int gw = (blk-128)*16 + warp;
            for (int task = gw; task < NB*AT; task += 320){
                int b = task >> 7, a = task & (AT-1);
                const float* wrow = W_q + a*DR;
                const float* hv = h0n + b*DR;
                float s = 0.f;
                for (int k = lane*4; k < DR; k += 128)
                    s += dot4(*(const float4*)(wrow + k), *(const float4*)(hv + k));
                s = wredsum(s);
                if (lane == 0) g_q[b*AT + a] = s + attn_b[a];
            }
        }
        gridbar(++tok);
    }

    // tail: feat/stop for the last step (h1(149) in buf 0; attc(149) in buf 1)
    if (blk >= 128)
        do_feat(TDEC-1, g_h1 + 0, g_attc2 + 1*NB*DIN,
                feat_W, stop_W, stop_b, out, blk, warp, lane);
}

// ---------------- host launch ----------------
extern "C" void kernel_launch(void* const* d_in, const int* in_sizes, int n_in,
                              void* d_out, int out_size) {
    const float* memory  = (const float*)d_in[0];
    const int*   memlen  = (const int*)  d_in[1];
    const float* targets = (const float*)d_in[2];
    const float* W_mem   = (const float*)d_in[3];
    const float* W_q     = (const float*)d_in[4];
    const float* W_loc   = (const float*)d_in[5];
    const float* filt    = (const float*)d_in[6];
    const float* attn_v  = (const float*)d_in[7];
    const float* attn_b  = (const float*)d_in[8];
    const float* pre_W1  = (const float*)d_in[9];
    const float* pre_b1  = (const float*)d_in[10];
    const float* pre_W2  = (const float*)d_in[11];
    const float* pre_b2  = (const float*)d_in[12];
    const float* Wi0     = (const float*)d_in[13];
    const float* Wh0     = (const float*)d_in[14];
    const float* bl0     = (const float*)d_in[15];
    const float* Wi1     = (const float*)d_in[16];
    const float* Wh1     = (const float*)d_in[17];
    const float* bl1     = (const float*)d_in[18];
    const float* feat_W  = (const float*)d_in[19];
    const float* stop_W  = (const float*)d_in[20];
    const float* stop_b  = (const float*)d_in[21];
    float* out = (float*)d_out;

    // GB300/ATS: host-side &symbol is the host shadow; resolve device addresses.
    float *pm_d = nullptr, *prev_d = nullptr, *p1_d = nullptr, *p2_d = nullptr;
    cudaGetSymbolAddress((void**)&pm_d,   g_pm);
    cudaGetSymbolAddress((void**)&prev_d, g_prev);
    cudaGetSymbolAddress((void**)&p1_d,   g_p1);
    cudaGetSymbolAddress((void**)&p2_d,   g_p2);

    k_init<<<64, 256>>>(targets, attn_b, W_loc, filt);
    k_gemm<<<dim3(64,2), 256>>>(memory, DIN, W_mem, DIN, pm_d, AT, NB*TENC, AT, DIN, nullptr, 0);
    k_gemm<<<dim3(19,4), 256>>>(prev_d, OD,   pre_W1, OD,   p1_d, PREN, TDEC*NB, PREN, OD,   pre_b1, 1);
    k_gemm<<<dim3(19,4), 256>>>(p1_d,   PREN, pre_W2, PREN, p2_d, PREN, TDEC*NB, PREN, PREN, pre_b2, 1);

    k_decoder<<<GRID, 512>>>(memory, memlen, attn_v,
                             Wi0, Wh0, bl0, Wi1, Wh1, bl1,
                             feat_W, stop_W, stop_b, W_q, attn_b, out);
}